// round 12
// baseline (speedup 1.0000x reference)
#include <cuda_runtime.h>
#include <cstdint>

#define B 128
#define L 200
#define D 256
#define V_SIZE 50000
#define THREADS 256

#define SPLIT 4                        // score blocks per batch
#define ROWS_PER_BLK (L / SPLIT)       // 50
#define SCORE_BLOCKS (B * SPLIT)       // 512
#define SMAX_BLOCKS B                  // 128 (dedup + softmax)
#define NZERO 8                        // zero blocks per batch
#define ZERO_BLOCKS (B * NZERO)        // 1024
#define GRID (SCORE_BLOCKS + SMAX_BLOCKS + ZERO_BLOCKS)   // 1664
#define V4 (V_SIZE / 4)                // 12500 float4 per batch row

__device__ float g_scores[B * L];
__device__ float g_weights[B * L];
__device__ int   g_sidx[B * L];        // last-occurrence ? idx : -1
__device__ int   g_scnt[B];            // score-block arrivals (->4, reset by softmax blk)
__device__ int   g_ready[B];           // weights ready flag (reset by last zero blk)
__device__ int   g_zdone[B];           // zero-block consume count (reset by last)

__device__ __forceinline__ int ld_acquire(const int* p) {
    int v;
    asm volatile("ld.acquire.gpu.global.b32 %0, [%1];" : "=r"(v) : "l"(p) : "memory");
    return v;
}

__global__ void __launch_bounds__(THREADS, 8)
fused_single_kernel(const float* __restrict__ w_es,
                    const float* __restrict__ score_v,
                    const int* __restrict__ x,
                    float* __restrict__ out,
                    int write_tail)
{
    __shared__ __align__(16) float sv[D];
    __shared__ __align__(16) int   xsh[THREADS];
    __shared__ float redm[8];
    __shared__ float reds[8];

    int blk = blockIdx.x;
    int tid = threadIdx.x;
    int wid = tid >> 5;
    int lane = tid & 31;

    if (blk < SCORE_BLOCKS) {
        // ================= score block: 50 dot products =================
        int b = blk / SPLIT;
        int l0 = (blk % SPLIT) * ROWS_PER_BLK;

        sv[tid] = score_v[tid];        // D == THREADS
        __syncthreads();

        const float* base = w_es + ((size_t)b * L + l0) * D;
        const float4* sv4 = reinterpret_cast<const float4*>(sv);

        for (int l = wid; l < ROWS_PER_BLK; l += 8) {
            const float4* row4 = reinterpret_cast<const float4*>(base + (size_t)l * D);
            float acc = 0.f;
            #pragma unroll
            for (int k = 0; k < 2; k++) {
                int d = lane + 32 * k;
                float4 a = row4[d];
                float4 s = sv4[d];
                acc = fmaf(a.x, s.x, acc);
                acc = fmaf(a.y, s.y, acc);
                acc = fmaf(a.z, s.z, acc);
                acc = fmaf(a.w, s.w, acc);
            }
            #pragma unroll
            for (int off = 16; off > 0; off >>= 1)
                acc += __shfl_xor_sync(0xFFFFFFFF, acc, off);
            if (lane == 0) g_scores[(size_t)b * L + l0 + l] = acc;
        }

        __syncthreads();
        if (tid == 0) {
            __threadfence();           // release scores (few in-flight stores: cheap)
            atomicAdd(&g_scnt[b], 1);
        }
    } else if (blk < SCORE_BLOCKS + SMAX_BLOCKS) {
        // ============ dedup + softmax block for batch b ============
        int b = blk - SCORE_BLOCKS;

        // dedup scan overlaps with waiting for score blocks
        int xv = (tid < L) ? x[(size_t)b * L + tid] : -1;
        xsh[tid] = xv;
        __syncthreads();
        int last = 1;
        #pragma unroll 8
        for (int l = tid + 1; l < L; l++)
            last &= (xsh[l] != xv);
        int sidx = (last && (unsigned)xv < V_SIZE) ? xv : -1;
        if (tid < L) g_sidx[(size_t)b * L + tid] = sidx;

        // wait for all 4 score blocks of batch b
        if (tid == 0) {
            while (ld_acquire(&g_scnt[b]) < SPLIT) __nanosleep(40);
            g_scnt[b] = 0;             // reset for next replay
        }
        __syncthreads();

        float v = (tid < L) ? g_scores[(size_t)b * L + tid] : -3.402823466e38f;

        float m = v;
        #pragma unroll
        for (int off = 16; off > 0; off >>= 1)
            m = fmaxf(m, __shfl_xor_sync(0xFFFFFFFF, m, off));
        if (lane == 0) redm[wid] = m;
        __syncthreads();
        float mx = redm[0];
        #pragma unroll
        for (int i = 1; i < 8; i++) mx = fmaxf(mx, redm[i]);

        float e = (tid < L) ? __expf(v - mx) : 0.f;
        float s = e;
        #pragma unroll
        for (int off = 16; off > 0; off >>= 1)
            s += __shfl_xor_sync(0xFFFFFFFF, s, off);
        if (lane == 0) reds[wid] = s;
        __syncthreads();
        float tot = reds[0];
        #pragma unroll
        for (int i = 1; i < 8; i++) tot += reds[i];

        float w = e * (1.0f / tot);
        if (tid < L) {
            g_weights[(size_t)b * L + tid] = w;
            if (write_tail)
                out[(size_t)B * V_SIZE + (size_t)b * L + tid] = w;
        }
        __syncthreads();
        if (tid == 0) {
            __threadfence();           // release weights + sidx
            g_ready[b] = 1;
        }
    } else {
        // ============ zero + scatter block (b, z) ============
        int idx = blk - SCORE_BLOCKS - SMAX_BLOCKS;
        int b = idx / NZERO;
        int z = idx % NZERO;

        // zero my interleaved share of w_a row b (coalesced float4)
        float4* p = reinterpret_cast<float4*>(out + (size_t)b * V_SIZE);
        float4 zero = make_float4(0.f, 0.f, 0.f, 0.f);
        for (int i = z * THREADS + tid; i < V4; i += NZERO * THREADS)
            p[i] = zero;

        // wait for weights (softmax usually done long before zeroing finishes)
        __syncthreads();
        if (tid == 0) {
            while (ld_acquire(&g_ready[b]) == 0) __nanosleep(40);
        }
        __syncthreads();               // block-level acquire + orders zero stores

        // scatter pairs owned by this block: owner of float4 (sidx>>2) is
        // ((sidx>>2)>>8)&7 == (sidx>>10)&7 with the interleaved zero pattern.
        if (tid < L) {
            int   sidx = g_sidx[(size_t)b * L + tid];
            if (sidx >= 0 && (((unsigned)sidx >> 10) & 7) == (unsigned)z) {
                float w = g_weights[(size_t)b * L + tid];
                out[(size_t)b * V_SIZE + sidx] = w;
            }
        }

        // last consumer resets flags (replay-safe)
        __syncthreads();
        if (tid == 0) {
            int old = atomicAdd(&g_zdone[b], 1);
            if (old == NZERO - 1) {
                g_zdone[b] = 0;
                g_ready[b] = 0;
            }
        }
    }
}

extern "C" void kernel_launch(void* const* d_in, const int* in_sizes, int n_in,
                              void* d_out, int out_size)
{
    const float* w_es = (const float*)d_in[0];
    const float* score_v = (const float*)d_in[1];
    const int* x = (const int*)d_in[2];
    float* out = (float*)d_out;

    int write_tail = (out_size >= B * V_SIZE + B * L) ? 1 : 0;

    fused_single_kernel<<<GRID, THREADS>>>(w_es, score_v, x, out, write_tail);
}

// round 13
// speedup vs baseline: 1.2851x; 1.2851x over previous
#include <cuda_runtime.h>
#include <cstdint>

#define B 128
#define L 200
#define D 256
#define V_SIZE 50000
#define THREADS 256

#define SPLIT 4                        // score blocks per batch
#define ROWS_PER_BLK (L / SPLIT)       // 50
#define SCORE_BLOCKS (B * SPLIT)       // 512
#define DEDUP_BLOCKS B                 // 128
#define K1_GRID (SCORE_BLOCKS + DEDUP_BLOCKS)   // 640

#define NZERO 8                        // K2 blocks per batch
#define K2_GRID (B * NZERO)            // 1024
#define V4 (V_SIZE / 4)                // 12500 float4 per batch row

__device__ float g_scores[B * L];
__device__ int   g_sidx[B * L];        // last-occurrence ? idx : -1

// ============ K1: scores (pure read) + dedup ============
__global__ void __launch_bounds__(THREADS)
score_dedup_kernel(const float* __restrict__ w_es,
                   const float* __restrict__ score_v,
                   const int* __restrict__ x)
{
    __shared__ __align__(16) float sv[D];
    __shared__ __align__(16) int   xsh[THREADS];

    int blk = blockIdx.x;
    int tid = threadIdx.x;

    if (blk < SCORE_BLOCKS) {
        int b = blk / SPLIT;
        int l0 = (blk % SPLIT) * ROWS_PER_BLK;

        sv[tid] = score_v[tid];        // D == THREADS
        __syncthreads();

        int wid = tid >> 5;
        int lane = tid & 31;
        const float* base = w_es + ((size_t)b * L + l0) * D;
        const float4* sv4 = reinterpret_cast<const float4*>(sv);

        for (int l = wid; l < ROWS_PER_BLK; l += 8) {
            const float4* row4 = reinterpret_cast<const float4*>(base + (size_t)l * D);
            float acc = 0.f;
            #pragma unroll
            for (int k = 0; k < 2; k++) {
                int d = lane + 32 * k;
                float4 a = row4[d];
                float4 s = sv4[d];
                acc = fmaf(a.x, s.x, acc);
                acc = fmaf(a.y, s.y, acc);
                acc = fmaf(a.z, s.z, acc);
                acc = fmaf(a.w, s.w, acc);
            }
            #pragma unroll
            for (int off = 16; off > 0; off >>= 1)
                acc += __shfl_xor_sync(0xFFFFFFFF, acc, off);
            if (lane == 0) g_scores[(size_t)b * L + l0 + l] = acc;
        }
    } else {
        // dedup: last-occurrence index row for batch b
        int b = blk - SCORE_BLOCKS;
        int xv = (tid < L) ? x[(size_t)b * L + tid] : -1;
        xsh[tid] = xv;
        __syncthreads();

        int last = 1;
        #pragma unroll 8
        for (int l = tid + 1; l < L; l++)
            last &= (xsh[l] != xv);

        if (tid < L)
            g_sidx[(size_t)b * L + tid] = (last && (unsigned)xv < V_SIZE) ? xv : -1;
    }
}

// ============ K2: zero (interleaved 1/8 row) + redundant softmax + scatter ============
__global__ void __launch_bounds__(THREADS)
zero_softmax_scatter_kernel(float* __restrict__ out, int write_tail)
{
    __shared__ float redm[8];
    __shared__ float reds[8];

    int blk = blockIdx.x;
    int tid = threadIdx.x;
    int wid = tid >> 5;
    int lane = tid & 31;
    int b = blk / NZERO;
    int z = blk % NZERO;

    // Issue the (L2-hot) score + sidx loads first so latency overlaps stores.
    float v    = (tid < L) ? g_scores[(size_t)b * L + tid] : -3.402823466e38f;
    int   sidx = (tid < L) ? g_sidx[(size_t)b * L + tid] : -1;

    // Zero my interleaved 1/8 of w_a row b (coalesced float4).
    float4* p = reinterpret_cast<float4*>(out + (size_t)b * V_SIZE);
    float4 zero = make_float4(0.f, 0.f, 0.f, 0.f);
    for (int i = z * THREADS + tid; i < V4; i += NZERO * THREADS)
        p[i] = zero;

    // Softmax (computed identically in all 8 blocks of this batch; overlaps
    // with the zero-store drain).
    float m = v;
    #pragma unroll
    for (int off = 16; off > 0; off >>= 1)
        m = fmaxf(m, __shfl_xor_sync(0xFFFFFFFF, m, off));
    if (lane == 0) redm[wid] = m;
    __syncthreads();
    float mx = redm[0];
    #pragma unroll
    for (int i = 1; i < 8; i++) mx = fmaxf(mx, redm[i]);

    float e = (tid < L) ? __expf(v - mx) : 0.f;
    float s = e;
    #pragma unroll
    for (int off = 16; off > 0; off >>= 1)
        s += __shfl_xor_sync(0xFFFFFFFF, s, off);
    if (lane == 0) reds[wid] = s;
    __syncthreads();
    float tot = reds[0];
    #pragma unroll
    for (int i = 1; i < 8; i++) tot += reds[i];

    float w = e * (1.0f / tot);

    // Order this block's zero stores before its scatter stores (block-scope
    // global ordering via __syncthreads; same block wrote the zeroes it may
    // overwrite — ownership below guarantees that).
    __syncthreads();

    if (tid < L) {
        if (z == 0 && write_tail)
            out[(size_t)B * V_SIZE + (size_t)b * L + tid] = w;
        // Owner of float4 chunk (sidx>>2) in the interleaved pattern:
        // ((sidx>>2)>>8)&7 == (sidx>>10)&7
        if (sidx >= 0 && (((unsigned)sidx >> 10) & 7) == (unsigned)z)
            out[(size_t)b * V_SIZE + sidx] = w;
    }
}

extern "C" void kernel_launch(void* const* d_in, const int* in_sizes, int n_in,
                              void* d_out, int out_size)
{
    const float* w_es = (const float*)d_in[0];
    const float* score_v = (const float*)d_in[1];
    const int* x = (const int*)d_in[2];
    float* out = (float*)d_out;

    int write_tail = (out_size >= B * V_SIZE + B * L) ? 1 : 0;

    score_dedup_kernel<<<K1_GRID, THREADS>>>(w_es, score_v, x);
    zero_softmax_scatter_kernel<<<K2_GRID, THREADS>>>(out, write_tail);
}

// round 15
// speedup vs baseline: 1.4608x; 1.1367x over previous
#include <cuda_runtime.h>
#include <cstdint>

#define B 128
#define L 200
#define D 256
#define V_SIZE 50000
#define THREADS 256

#define SPLIT 4                       // score blocks per batch
#define ROWS_PER_BLK (L / SPLIT)      // 50
#define SCORE_BLOCKS (B * SPLIT)      // 512
#define ZERO_BLOCKS 1024
#define DEDUP_BLOCKS B                // 128
#define K1_GRID (SCORE_BLOCKS + ZERO_BLOCKS + DEDUP_BLOCKS)   // 1664

__device__ float g_scores[B * L];
__device__ int   g_sidx[B * L];       // last-occurrence ? idx : -1

// K1: [0,512) score blocks; [512,1536) zero blocks; [1536,1664) dedup blocks.
// (Identical to the proven R10 kernel.)
__global__ void __launch_bounds__(THREADS)
stream_kernel(const float* __restrict__ w_es,
              const float* __restrict__ score_v,
              const int* __restrict__ x,
              float* __restrict__ out)
{
    __shared__ __align__(16) float sv[D];
    __shared__ __align__(16) int   xsh[THREADS];

    int blk = blockIdx.x;
    int tid = threadIdx.x;

    if (blk < SCORE_BLOCKS) {
        int b = blk / SPLIT;
        int l0 = (blk % SPLIT) * ROWS_PER_BLK;

        sv[tid] = score_v[tid];       // D == THREADS
        __syncthreads();

        int wid = tid >> 5;
        int lane = tid & 31;
        const float* base = w_es + ((size_t)b * L + l0) * D;
        const float4* sv4 = reinterpret_cast<const float4*>(sv);

        for (int l = wid; l < ROWS_PER_BLK; l += 8) {
            const float4* row4 = reinterpret_cast<const float4*>(base + (size_t)l * D);
            float acc = 0.f;
            #pragma unroll
            for (int k = 0; k < 2; k++) {
                int d = lane + 32 * k;
                float4 a = row4[d];
                float4 s = sv4[d];
                acc = fmaf(a.x, s.x, acc);
                acc = fmaf(a.y, s.y, acc);
                acc = fmaf(a.z, s.z, acc);
                acc = fmaf(a.w, s.w, acc);
            }
            #pragma unroll
            for (int off = 16; off > 0; off >>= 1)
                acc += __shfl_xor_sync(0xFFFFFFFF, acc, off);
            if (lane == 0) g_scores[(size_t)b * L + l0 + l] = acc;
        }
    } else if (blk < SCORE_BLOCKS + ZERO_BLOCKS) {
        size_t total4 = ((size_t)B * V_SIZE) / 4;          // 1,600,000
        float4* p = reinterpret_cast<float4*>(out);
        size_t idx = (size_t)(blk - SCORE_BLOCKS) * THREADS + tid;
        size_t stride = (size_t)ZERO_BLOCKS * THREADS;
        float4 z = make_float4(0.f, 0.f, 0.f, 0.f);
        for (; idx < total4; idx += stride) p[idx] = z;
    } else {
        int b = blk - SCORE_BLOCKS - ZERO_BLOCKS;
        int xv = (tid < L) ? x[(size_t)b * L + tid] : -1;
        xsh[tid] = xv;
        __syncthreads();

        int last = 1;
        #pragma unroll 8
        for (int l = tid + 1; l < L; l++)
            last &= (xsh[l] != xv);

        if (tid < L)
            g_sidx[(size_t)b * L + tid] = (last && (unsigned)xv < V_SIZE) ? xv : -1;
    }
}

// K2: softmax + masked scatter. With PDL, blocks spin up during K1 and
// cudaGridDependencySynchronize() gates on K1 completion + visibility.
// Without PDL (fallback), the call returns immediately — still correct.
__global__ void __launch_bounds__(THREADS)
softmax_scatter_kernel(float* __restrict__ out, int write_tail)
{
    int b = blockIdx.x;
    int tid = threadIdx.x;
    int wid = tid >> 5;
    int lane = tid & 31;

    __shared__ float redm[8];
    __shared__ float reds[8];

    cudaGridDependencySynchronize();

    float v    = (tid < L) ? g_scores[(size_t)b * L + tid] : -3.402823466e38f;
    int   sidx = (tid < L) ? g_sidx[(size_t)b * L + tid] : -1;

    float m = v;
    #pragma unroll
    for (int off = 16; off > 0; off >>= 1)
        m = fmaxf(m, __shfl_xor_sync(0xFFFFFFFF, m, off));
    if (lane == 0) redm[wid] = m;
    __syncthreads();
    float mx = redm[0];
    #pragma unroll
    for (int i = 1; i < 8; i++) mx = fmaxf(mx, redm[i]);

    float e = (tid < L) ? __expf(v - mx) : 0.f;
    float s = e;
    #pragma unroll
    for (int off = 16; off > 0; off >>= 1)
        s += __shfl_xor_sync(0xFFFFFFFF, s, off);
    if (lane == 0) reds[wid] = s;
    __syncthreads();
    float tot = reds[0];
    #pragma unroll
    for (int i = 1; i < 8; i++) tot += reds[i];

    float w = e * (1.0f / tot);

    if (tid < L) {
        if (write_tail)
            out[(size_t)B * V_SIZE + (size_t)b * L + tid] = w;
        if (sidx >= 0)
            out[(size_t)b * V_SIZE + sidx] = w;
    }
}

extern "C" void kernel_launch(void* const* d_in, const int* in_sizes, int n_in,
                              void* d_out, int out_size)
{
    const float* w_es = (const float*)d_in[0];
    const float* score_v = (const float*)d_in[1];
    const int* x = (const int*)d_in[2];
    float* out = (float*)d_out;

    int write_tail = (out_size >= B * V_SIZE + B * L) ? 1 : 0;

    stream_kernel<<<K1_GRID, THREADS>>>(w_es, score_v, x, out);

    // K2 with programmatic dependent launch; fall back to a plain launch if
    // the attributed launch is rejected (e.g., unsupported under capture).
    cudaLaunchAttribute attrs[1];
    attrs[0].id = cudaLaunchAttributeProgrammaticStreamSerialization;
    attrs[0].val.programmaticStreamSerializationAllowed = 1;

    cudaLaunchConfig_t cfg = {};
    cfg.gridDim = dim3(B, 1, 1);
    cfg.blockDim = dim3(THREADS, 1, 1);
    cfg.dynamicSmemBytes = 0;
    cfg.stream = 0;
    cfg.attrs = attrs;
    cfg.numAttrs = 1;

    cudaError_t err = cudaLaunchKernelEx(&cfg, softmax_scatter_kernel, out, write_tail);
    if (err != cudaSuccess) {
        (void)cudaGetLastError();     // clear sticky error state
        softmax_scatter_kernel<<<B, THREADS>>>(out, write_tail);
    }
}